// round 4
// baseline (speedup 1.0000x reference)
#include <cuda_runtime.h>

#define DD      4096     // embedding dim
#define RNK     16       // LoRA rank
#define SEQ     512      // sequence length
#define SPLIT   32       // first 32 positions use img router
#define SCALE   2.0f     // lora_alpha / r
#define T_TILE  32       // tokens per block
#define THREADS 256      // each thread owns 4 consecutive d -> 1024-wide d tile
#define PF      4        // base-gather ring depth (tokens)

typedef unsigned long long ull;

__device__ __forceinline__ ull pk(float lo, float hi) {
    ull r; asm("mov.b64 %0,{%1,%2};" : "=l"(r) : "f"(lo), "f"(hi)); return r;
}
__device__ __forceinline__ void upk(ull v, float& lo, float& hi) {
    asm("mov.b64 {%0,%1},%2;" : "=f"(lo), "=f"(hi) : "l"(v));
}
// Blackwell packed fp32x2 FMA: d = a*b + c on both halves
__device__ __forceinline__ ull fma2(ull a, ull b, ull c) {
    ull r; asm("fma.rn.f32x2 %0,%1,%2,%3;" : "=l"(r) : "l"(a), "l"(b), "l"(c)); return r;
}

// Rows d0..d0+3 of Bm ([D,16] row-major), packed cross-row:
// bpA[s+j] = (Bm[d0][j], Bm[d0+1][j]);  bpB[s+j] = (Bm[d0+2][j], Bm[d0+3][j])
__device__ __forceinline__ void load_bpairs(const float* __restrict__ Bm, int d0,
                                            ull* bpA, ull* bpB) {
    const float4* p0 = reinterpret_cast<const float4*>(Bm + (size_t)(d0 + 0) * RNK);
    const float4* p1 = reinterpret_cast<const float4*>(Bm + (size_t)(d0 + 1) * RNK);
    const float4* p2 = reinterpret_cast<const float4*>(Bm + (size_t)(d0 + 2) * RNK);
    const float4* p3 = reinterpret_cast<const float4*>(Bm + (size_t)(d0 + 3) * RNK);
#pragma unroll
    for (int q = 0; q < 4; ++q) {
        float4 v0 = p0[q], v1 = p1[q], v2 = p2[q], v3 = p3[q];
        bpA[4 * q + 0] = pk(v0.x, v1.x);  bpB[4 * q + 0] = pk(v2.x, v3.x);
        bpA[4 * q + 1] = pk(v0.y, v1.y);  bpB[4 * q + 1] = pk(v2.y, v3.y);
        bpA[4 * q + 2] = pk(v0.z, v1.z);  bpB[4 * q + 2] = pk(v2.z, v3.z);
        bpA[4 * q + 3] = pk(v0.w, v1.w);  bpB[4 * q + 3] = pk(v2.w, v3.w);
    }
}

__global__ __launch_bounds__(THREADS, 1)
void moe_emb_kernel(const int* __restrict__ xg,
                    const float* __restrict__ emb,
                    const float* __restrict__ A1, const float* __restrict__ B1,
                    const float* __restrict__ A2, const float* __restrict__ B2,
                    const float* __restrict__ WrI, const float* __restrict__ brI,
                    const float* __restrict__ WrT, const float* __restrict__ brT,
                    float* __restrict__ out, int V, int n_tok)
{
    __shared__ __align__(16) float scoef[T_TILE * 32];  // unduplicated: 32 coefs/token
    __shared__ int   sx[T_TILE];
    __shared__ float sw[T_TILE * 2];

    const int tid = threadIdx.x;
    const int t0  = blockIdx.y * T_TILE;
    const int d0  = blockIdx.x * (THREADS * 4) + tid * 4;

    // ---- B pair registers (L2-hot; overlaps phase-1 latency) ----
    ull bpA[32], bpB[32];                 // slots 0..15 = B1, 16..31 = B2
    load_bpairs(B1, d0, bpA, bpB);
    load_bpairs(B2, d0, bpA + 16, bpB + 16);

    // ---- phase 1a: per-token router weights (softmax over 2 logits) ----
    if (tid < T_TILE) {
        int tg = t0 + tid;
        int tr = (tg < n_tok) ? tg : (n_tok - 1);
        int xi = xg[tr];
        xi = (xi < 0) ? 0 : ((xi >= V) ? V - 1 : xi);
        sx[tid] = xi;
        bool img = ((tg % SEQ) < SPLIT);
        const float* Wr = img ? WrI : WrT;
        const float* br = img ? brI : brT;
        float l0 = Wr[xi] + br[0];
        float l1 = Wr[(size_t)V + xi] + br[1];
        float w0 = 1.0f / (1.0f + __expf(l1 - l0));
        sw[2 * tid]     = w0;
        sw[2 * tid + 1] = 1.0f - w0;
    }
    __syncthreads();

    // ---- phase 1b: coefficients c[t][j] = w * 2.0 * A[j][x] (unduplicated) ----
    for (int i = tid; i < T_TILE * 32; i += THREADS) {
        int t = i >> 5, j = i & 31;
        int xi = sx[t];
        float c;
        if (j < 16) c = sw[2 * t]     * SCALE * __ldg(A1 + (size_t)j * V + xi);
        else        c = sw[2 * t + 1] * SCALE * __ldg(A2 + (size_t)(j - 16) * V + xi);
        scoef[t * 32 + j] = c;
    }
    __syncthreads();

    // ---- phase 2: base gather (4-deep ring) + rank-32 update via FFMA2 ----
    float4 ring[PF];
#pragma unroll
    for (int u = 0; u < PF; ++u)
        ring[u] = __ldcs(reinterpret_cast<const float4*>(emb + (size_t)sx[u] * DD + d0));

#pragma unroll 2
    for (int t = 0; t < T_TILE; ++t) {
        float4 base = ring[t & (PF - 1)];
        int tn = t + PF;
        if (tn < T_TILE)
            ring[t & (PF - 1)] =
                __ldcs(reinterpret_cast<const float4*>(emb + (size_t)sx[tn] * DD + d0));

        // issue all 8 coefficient loads up front (ILP covers LDS latency)
        const float4* cp4 = reinterpret_cast<const float4*>(scoef + t * 32);
        float4 q[8];
#pragma unroll
        for (int jj = 0; jj < 8; ++jj) q[jj] = cp4[jj];

        ull acc0 = pk(base.x, base.y);
        ull acc1 = pk(base.z, base.w);
#pragma unroll
        for (int jj = 0; jj < 8; ++jj) {
            ull cc;
            cc = pk(q[jj].x, q[jj].x);
            acc0 = fma2(bpA[4 * jj + 0], cc, acc0);
            acc1 = fma2(bpB[4 * jj + 0], cc, acc1);
            cc = pk(q[jj].y, q[jj].y);
            acc0 = fma2(bpA[4 * jj + 1], cc, acc0);
            acc1 = fma2(bpB[4 * jj + 1], cc, acc1);
            cc = pk(q[jj].z, q[jj].z);
            acc0 = fma2(bpA[4 * jj + 2], cc, acc0);
            acc1 = fma2(bpB[4 * jj + 2], cc, acc1);
            cc = pk(q[jj].w, q[jj].w);
            acc0 = fma2(bpA[4 * jj + 3], cc, acc0);
            acc1 = fma2(bpB[4 * jj + 3], cc, acc1);
        }
        float o0, o1, o2, o3;
        upk(acc0, o0, o1); upk(acc1, o2, o3);
        if (t0 + t < n_tok)
            __stcs(reinterpret_cast<float4*>(out + (size_t)(t0 + t) * DD + d0),
                   make_float4(o0, o1, o2, o3));
    }
}

extern "C" void kernel_launch(void* const* d_in, const int* in_sizes, int n_in,
                              void* d_out, int out_size) {
    const int*   x   = (const int*)d_in[0];
    const float* emb = (const float*)d_in[1];
    const float* A1  = (const float*)d_in[2];
    const float* B1  = (const float*)d_in[3];
    const float* A2  = (const float*)d_in[4];
    const float* B2  = (const float*)d_in[5];
    const float* WrI = (const float*)d_in[6];
    const float* brI = (const float*)d_in[7];
    const float* WrT = (const float*)d_in[8];
    const float* brT = (const float*)d_in[9];
    float* out = (float*)d_out;

    const int E  = in_sizes[7];            // 4
    const int V  = in_sizes[6] / E;        // 32000
    const int BS = in_sizes[0];            // 4096 tokens

    dim3 grid(DD / (4 * THREADS), (BS + T_TILE - 1) / T_TILE);
    moe_emb_kernel<<<grid, THREADS>>>(x, emb, A1, B1, A2, B2,
                                      WrI, brI, WrT, brT, out, V, BS);
}

// round 5
// speedup vs baseline: 1.7623x; 1.7623x over previous
#include <cuda_runtime.h>

#define DD      4096     // embedding dim
#define RNK     16       // LoRA rank
#define SEQ     512      // sequence length
#define SPLIT   32       // first 32 positions use img router
#define SCALE   2.0f     // lora_alpha / r
#define T_TILE  32       // tokens per block
#define THREADS 256      // each thread owns 2 consecutive d -> 512-wide d tile
#define PF      8        // base-gather ring depth (tokens)

typedef unsigned long long ull;

__device__ __forceinline__ ull pk(float lo, float hi) {
    ull r; asm("mov.b64 %0,{%1,%2};" : "=l"(r) : "f"(lo), "f"(hi)); return r;
}
__device__ __forceinline__ void upk(ull v, float& lo, float& hi) {
    asm("mov.b64 {%0,%1},%2;" : "=f"(lo), "=f"(hi) : "l"(v));
}
// Blackwell packed fp32x2 FMA: d = a*b + c on both halves
__device__ __forceinline__ ull fma2(ull a, ull b, ull c) {
    ull r; asm("fma.rn.f32x2 %0,%1,%2,%3;" : "=l"(r) : "l"(a), "l"(b), "l"(c)); return r;
}

// Rows d0, d0+1 of Bm ([D,16] row-major), packed cross-row:
// bp[j] = (Bm[d0][j], Bm[d0+1][j]),  j = 0..15
__device__ __forceinline__ void load_bpairs(const float* __restrict__ Bm, int d0, ull* bp) {
    const float4* p0 = reinterpret_cast<const float4*>(Bm + (size_t)d0 * RNK);
    const float4* p1 = reinterpret_cast<const float4*>(Bm + (size_t)(d0 + 1) * RNK);
#pragma unroll
    for (int q = 0; q < 4; ++q) {
        float4 v0 = p0[q]; float4 v1 = p1[q];
        bp[4 * q + 0] = pk(v0.x, v1.x);
        bp[4 * q + 1] = pk(v0.y, v1.y);
        bp[4 * q + 2] = pk(v0.z, v1.z);
        bp[4 * q + 3] = pk(v0.w, v1.w);
    }
}

__global__ __launch_bounds__(THREADS, 2)
void moe_emb_kernel(const int* __restrict__ xg,
                    const float* __restrict__ emb,
                    const float* __restrict__ A1, const float* __restrict__ B1,
                    const float* __restrict__ A2, const float* __restrict__ B2,
                    const float* __restrict__ WrI, const float* __restrict__ brI,
                    const float* __restrict__ WrT, const float* __restrict__ brT,
                    float* __restrict__ out, int V, int n_tok)
{
    __shared__ __align__(16) float scoef[T_TILE * 32];  // unduplicated: 32 coefs/token
    __shared__ int   sx[T_TILE];
    __shared__ float sw[T_TILE * 2];

    const int tid = threadIdx.x;
    const int t0  = blockIdx.y * T_TILE;
    const int d0  = blockIdx.x * (THREADS * 2) + tid * 2;

    // ---- B pair registers (L2-hot; overlaps phase-1 latency) ----
    ull bp[32];                         // slots 0..15 = B1 rows d0..d0+1, 16..31 = B2
    load_bpairs(B1, d0, bp);
    load_bpairs(B2, d0, bp + 16);

    // ---- phase 1a: per-token router weights (softmax over 2 logits) ----
    if (tid < T_TILE) {
        int tg = t0 + tid;
        int tr = (tg < n_tok) ? tg : (n_tok - 1);
        int xi = xg[tr];
        xi = (xi < 0) ? 0 : ((xi >= V) ? V - 1 : xi);   // safety clamp
        sx[tid] = xi;
        bool img = ((tg % SEQ) < SPLIT);
        const float* Wr = img ? WrI : WrT;
        const float* br = img ? brI : brT;
        float l0 = Wr[xi] + br[0];
        float l1 = Wr[(size_t)V + xi] + br[1];
        float w0 = 1.0f / (1.0f + __expf(l1 - l0));
        sw[2 * tid]     = w0;
        sw[2 * tid + 1] = 1.0f - w0;
    }
    __syncthreads();

    // ---- phase 1b: coefficients c[t][j] = w * 2.0 * A[j][x] (unduplicated) ----
    for (int i = tid; i < T_TILE * 32; i += THREADS) {
        int t = i >> 5, j = i & 31;
        int xi = sx[t];
        float c;
        if (j < 16) c = sw[2 * t]     * SCALE * __ldg(A1 + (size_t)j * V + xi);
        else        c = sw[2 * t + 1] * SCALE * __ldg(A2 + (size_t)(j - 16) * V + xi);
        scoef[t * 32 + j] = c;
    }
    __syncthreads();

    // ---- phase 2: base gather (8-deep ring) + rank-32 update via FFMA2 ----
    float2 ring[PF];
#pragma unroll
    for (int u = 0; u < PF; ++u)
        ring[u] = *reinterpret_cast<const float2*>(emb + (size_t)sx[u] * DD + d0);

#pragma unroll 1
    for (int g = 0; g < T_TILE; g += PF) {
#pragma unroll
        for (int u = 0; u < PF; ++u) {
            const int t = g + u;
            float2 base = ring[u];
            int tn = t + PF;
            if (tn < T_TILE)   // refill ring slot -> keeps PF loads in flight
                ring[u] = *reinterpret_cast<const float2*>(emb + (size_t)sx[tn] * DD + d0);

            ull acc = pk(base.x, base.y);
            const float4* cp4 = reinterpret_cast<const float4*>(scoef + t * 32);
#pragma unroll
            for (int jj = 0; jj < 8; ++jj) {      // 1 LDS.128 -> 4 coefs -> 4 fma2
                float4 q = cp4[jj];
                acc = fma2(bp[4 * jj + 0], pk(q.x, q.x), acc);
                acc = fma2(bp[4 * jj + 1], pk(q.y, q.y), acc);
                acc = fma2(bp[4 * jj + 2], pk(q.z, q.z), acc);
                acc = fma2(bp[4 * jj + 3], pk(q.w, q.w), acc);
            }
            float o0, o1;
            upk(acc, o0, o1);
            if (t0 + t < n_tok)
                *reinterpret_cast<float2*>(out + (size_t)(t0 + t) * DD + d0) =
                    make_float2(o0, o1);
        }
    }
}

extern "C" void kernel_launch(void* const* d_in, const int* in_sizes, int n_in,
                              void* d_out, int out_size) {
    const int*   x   = (const int*)d_in[0];
    const float* emb = (const float*)d_in[1];
    const float* A1  = (const float*)d_in[2];
    const float* B1  = (const float*)d_in[3];
    const float* A2  = (const float*)d_in[4];
    const float* B2  = (const float*)d_in[5];
    const float* WrI = (const float*)d_in[6];
    const float* brI = (const float*)d_in[7];
    const float* WrT = (const float*)d_in[8];
    const float* brT = (const float*)d_in[9];
    float* out = (float*)d_out;

    const int E  = in_sizes[7];            // 4
    const int V  = in_sizes[6] / E;        // 32000
    const int BS = in_sizes[0];            // 4096 tokens

    dim3 grid(DD / (2 * THREADS), (BS + T_TILE - 1) / T_TILE);
    moe_emb_kernel<<<grid, THREADS>>>(x, emb, A1, B1, A2, B2,
                                      WrI, brI, WrT, brT, out, V, BS);
}